// round 4
// baseline (speedup 1.0000x reference)
#include <cuda_runtime.h>
#include <cuda_bf16.h>
#include <math.h>

// ---------------------------------------------------------------------------
// InstantNGP hash-grid embedding, 16 levels, F=2, T=2^19, 1M points.
//
// R4 changes vs R3 (366.7us, L1=87.6% binding):
//  * pair-load: dim0 prime is 1 => for even u0 the two x-corners are the
//    aligned table pair {h,h^1} in ONE 32B sector; fetch with a single
//    float4 (1 wavefront instead of 2). Odd u0 falls back to a predicated
//    float2 load. ~25% fewer load wavefronts.
//  * smem-staged output: per-level results go to shared (stride-34 rows),
//    then a conflict-free block-strided copy does fully coalesced STG.32.
//    Store wavefronts drop 256 -> ~32 per warp AND the 32-reg accumulator
//    array disappears (occupancy 45% -> ~65%+).
// ---------------------------------------------------------------------------

#define NLVL 16
#define LOG2_T 19
#define TABLE_SIZE (1u << LOG2_T)
#define HMASK (TABLE_SIZE - 1u)
#define BSZ 1048576
#define PRIME1 2654435761u
#define PRIME2 805459861u
#define TPB 256
#define SROW 34   // floats per smem row (32 data + 2 pad; conflict-bounded)

struct LevelParams {
    float invgs;   // 1 / grid_size (host-computed via double)
    float resm1;   // (float)(res - 1)
};
struct AllParams {
    LevelParams lp[NLVL];
};

__global__ __launch_bounds__(TPB)
void hash_embed_kernel(const float* __restrict__ x,
                       const float* __restrict__ emb,
                       float* __restrict__ out,
                       AllParams P)
{
    __shared__ float s[TPB * SROW];

    const int tid = threadIdx.x;
    const int p = blockIdx.x * TPB + tid;      // BSZ % TPB == 0

    const float x0 = __ldg(&x[p * 3 + 0]);
    const float x1 = __ldg(&x[p * 3 + 1]);
    const float x2 = __ldg(&x[p * 3 + 2]);

    float* srow = &s[tid * SROW];

#pragma unroll 1
    for (int l = 0; l < NLVL; ++l) {
        const float invgs = P.lp[l].invgs;
        const float rm1   = P.lp[l].resm1;

        const float rel0 = (x0 + 1.0f) * invgs;
        const float rel1 = (x1 + 1.0f) * invgs;
        const float rel2 = (x2 + 1.0f) * invgs;

        const float f0 = fminf(fmaxf(floorf(rel0), 0.0f), rm1);
        const float f1 = fminf(fmaxf(floorf(rel1), 0.0f), rm1);
        const float f2 = fminf(fmaxf(floorf(rel2), 0.0f), rm1);

        const float w0 = rel0 - f0;
        const float w1 = rel1 - f1;
        const float w2 = rel2 - f2;

        const unsigned u0 = (unsigned)f0;
        const unsigned u1 = (unsigned)f1;
        const unsigned u2 = (unsigned)f2;

        const bool odd0 = (u0 & 1u) != 0u;   // parity decides pair-load validity

        const unsigned a0 = u0;
        const unsigned a1 = u0 + 1u;
        const unsigned b0 = u1 * PRIME1;
        const unsigned b1 = b0 + PRIME1;
        const unsigned c0 = u2 * PRIME2;
        const unsigned c1 = c0 + PRIME2;

        const float2* __restrict__ tab =
            (const float2*)emb + (size_t)l * TABLE_SIZE;
        const float4* __restrict__ tab4 = (const float4*)tab;

        // hash of x-corner 0 for each (y,z) combo; x-corner 1 = hash of a1
        const unsigned hA00 = (a0 ^ b0 ^ c0) & HMASK;
        const unsigned hA10 = (a0 ^ b1 ^ c0) & HMASK;
        const unsigned hA01 = (a0 ^ b0 ^ c1) & HMASK;
        const unsigned hA11 = (a0 ^ b1 ^ c1) & HMASK;

        // pair loads: float4 covers entries {hA&~1, hA|1}; if u0 even this is
        // exactly {corner_x0, corner_x1} (in some order). 4 wavefronts.
        const float4 q00 = __ldg(&tab4[hA00 >> 1]);
        const float4 q10 = __ldg(&tab4[hA10 >> 1]);
        const float4 q01 = __ldg(&tab4[hA01 >> 1]);
        const float4 q11 = __ldg(&tab4[hA11 >> 1]);

        const bool o00 = (hA00 & 1u) != 0u;
        const bool o10 = (hA10 & 1u) != 0u;
        const bool o01 = (hA01 & 1u) != 0u;
        const bool o11 = (hA11 & 1u) != 0u;

        float2 vA00 = o00 ? make_float2(q00.z, q00.w) : make_float2(q00.x, q00.y);
        float2 vA10 = o10 ? make_float2(q10.z, q10.w) : make_float2(q10.x, q10.y);
        float2 vA01 = o01 ? make_float2(q01.z, q01.w) : make_float2(q01.x, q01.y);
        float2 vA11 = o11 ? make_float2(q11.z, q11.w) : make_float2(q11.x, q11.y);

        // x-corner 1: other half of the pair (even u0) or a predicated load (odd)
        float2 vB00 = o00 ? make_float2(q00.x, q00.y) : make_float2(q00.z, q00.w);
        float2 vB10 = o10 ? make_float2(q10.x, q10.y) : make_float2(q10.z, q10.w);
        float2 vB01 = o01 ? make_float2(q01.x, q01.y) : make_float2(q01.z, q01.w);
        float2 vB11 = o11 ? make_float2(q11.x, q11.y) : make_float2(q11.z, q11.w);

        if (odd0) {
            vB00 = __ldg(&tab[(a1 ^ b0 ^ c0) & HMASK]);
            vB10 = __ldg(&tab[(a1 ^ b1 ^ c0) & HMASK]);
            vB01 = __ldg(&tab[(a1 ^ b0 ^ c1) & HMASK]);
            vB11 = __ldg(&tab[(a1 ^ b1 ^ c1) & HMASK]);
        }

        const float m0 = 1.0f - w0;
        const float m1 = 1.0f - w1;
        const float m2 = 1.0f - w2;

        const float p00 = m1 * m2;
        const float p10 = w1 * m2;
        const float p01 = m1 * w2;
        const float p11 = w1 * w2;

        // combine the two x-corners first (shared (y,z) weight), then blend
        float cx00x = fmaf(w0, vB00.x, m0 * vA00.x);
        float cx00y = fmaf(w0, vB00.y, m0 * vA00.y);
        float cx10x = fmaf(w0, vB10.x, m0 * vA10.x);
        float cx10y = fmaf(w0, vB10.y, m0 * vA10.y);
        float cx01x = fmaf(w0, vB01.x, m0 * vA01.x);
        float cx01y = fmaf(w0, vB01.y, m0 * vA01.y);
        float cx11x = fmaf(w0, vB11.x, m0 * vA11.x);
        float cx11y = fmaf(w0, vB11.y, m0 * vA11.y);

        float accx = p00 * cx00x;
        float accy = p00 * cx00y;
        accx = fmaf(p10, cx10x, accx);
        accy = fmaf(p10, cx10y, accy);
        accx = fmaf(p01, cx01x, accx);
        accy = fmaf(p01, cx01y, accy);
        accx = fmaf(p11, cx11x, accx);
        accy = fmaf(p11, cx11y, accy);

        srow[2 * l]     = accx;
        srow[2 * l + 1] = accy;

        // phase-lock the block on one level at a time (L1 table locality);
        // the final iteration's barrier also guards the copy-out below.
        __syncthreads();
    }

    // coalesced copy-out: lane e of the warp reads element e of one point's
    // row per iteration (banks (34*row + e) % 32 all distinct -> conflict-free),
    // and the STG.32 across the warp is one contiguous 128B line.
    const int base = blockIdx.x * (TPB * 32);
#pragma unroll
    for (int k = tid; k < TPB * 32; k += TPB) {
        out[base + k] = s[(k >> 5) * SROW + (k & 31)];
    }
}

extern "C" void kernel_launch(void* const* d_in, const int* in_sizes, int n_in,
                              void* d_out, int out_size)
{
    const float* x   = (const float*)d_in[0];   // (1048576, 3) f32
    const float* emb = (const float*)d_in[1];   // (16, 524288, 2) f32
    float* out = (float*)d_out;                 // (1048576, 32) f32

    // Recompute RESOLUTIONS with the reference's double-precision formula
    // (several floor() results sit exactly on integer boundaries).
    AllParams P;
    const double growth = exp((log(512.0) - log(16.0)) / 15.0);
    for (int i = 0; i < NLVL; ++i) {
        int res = (int)floor(16.0 * pow(growth, (double)i));
        float gsf = (float)(2.0 / (double)res);
        P.lp[i].invgs = (float)(1.0 / (double)gsf);
        P.lp[i].resm1 = (float)(res - 1);
    }

    dim3 grid(BSZ / TPB);
    dim3 block(TPB);
    hash_embed_kernel<<<grid, block>>>(x, emb, out, P);
}